// round 2
// baseline (speedup 1.0000x reference)
#include <cuda_runtime.h>
#include <math.h>

// ---------------------------------------------------------------------------
// ColorHistogramMatchingLoss
//   x, y: (8, 3, 256, 256) fp32.  Per (image, batch, channel) build a 64x64
//   histogram: hist[u,v] = sum_px i_y * K(uc-center_u) * K(vc-center_v),
//   K(d) = 1/(1+(d/0.02)^2).  Then Hellinger-style distance -> scalar.
//
// Strategy: the histogram is a GEMM (64 x 64, K=65536) with on-the-fly
// generated operands. Stage per-pixel RBF rows in shared memory (Ku stored
// DUPLICATED so LDS.128 yields (a,a) pairs), accumulate with packed
// fma.rn.f32x2 (2 fp32 FMA / instr on sm_103a). 16 chunks per histogram for
// parallelism; partials reduced + final scalar in two small kernels.
// ---------------------------------------------------------------------------

#define NB        8
#define DH        64
#define CHUNKS    16
#define CHUNK_PIX 4096
#define SG_PIX    1024
#define GRP       32
#define NPIX      65536
#define TOT_BLOCKS (2 * NB * 3 * CHUNKS)   // 768

__device__ float g_part[(size_t)TOT_BLOCKS * DH * DH];   // 12.6 MB partials
__device__ float g_hist[(size_t)2 * NB * 3 * DH * DH];   // final 48 histograms
__device__ float g_tot[2 * NB * 3];                      // per-hist totals

#define FMA2(acc, a, b) \
    asm("fma.rn.f32x2 %0, %1, %2, %0;" : "+l"(acc) : "l"(a), "l"(b))

__device__ __forceinline__ float lo32(unsigned long long a) {
    return __uint_as_float((unsigned int)a);
}
__device__ __forceinline__ float hi32(unsigned long long a) {
    return __uint_as_float((unsigned int)(a >> 32));
}

__global__ __launch_bounds__(256) void hist_kernel(const float* __restrict__ x,
                                                   const float* __restrict__ y) {
    __shared__ float u_s[SG_PIX];
    __shared__ float v_s[SG_PIX];
    __shared__ float w_s[SG_PIX];
    __shared__ float ku[GRP * 2 * DH];   // duplicated: 32 x 128 floats
    __shared__ float kv[GRP * DH];       // 32 x 64 floats

    const int bid   = blockIdx.x;
    const int img   = bid / (NB * 3 * CHUNKS);
    const int rem   = bid % (NB * 3 * CHUNKS);
    const int b     = rem / (3 * CHUNKS);
    const int rem2  = rem % (3 * CHUNKS);
    const int ch    = rem2 / CHUNKS;
    const int chunk = rem2 % CHUNKS;

    const float* base = img ? y : x;
    const float* pr = base + (size_t)(b * 3 + 0) * NPIX + chunk * CHUNK_PIX;
    const float* pg = base + (size_t)(b * 3 + 1) * NPIX + chunk * CHUNK_PIX;
    const float* pb = base + (size_t)(b * 3 + 2) * NPIX + chunk * CHUNK_PIX;

    const int t  = threadIdx.x;
    const int j  = t & 63;                       // bin owned in eval phase
    const float c50 = (float)j * (300.0f / 63.0f) - 150.0f;  // 50 * center_j
    const int pbase = t >> 6;                    // 0..3
    const int tr = t >> 4;                       // 0..15  (u-tile row)
    const int tc = t & 15;                       // 0..15  (v-tile col)

    unsigned long long acc[4][2];
#pragma unroll
    for (int i = 0; i < 4; ++i) { acc[i][0] = 0ull; acc[i][1] = 0ull; }

    for (int sg = 0; sg < CHUNK_PIX / SG_PIX; ++sg) {
        __syncthreads();
        // ---- preprocess 1024 pixels: u, v, weight ----
#pragma unroll
        for (int q = 0; q < SG_PIX / 256; ++q) {
            const int p   = t + 256 * q;
            const int pix = sg * SG_PIX + p;
            float r  = pr[pix] + 1e-6f;
            float g  = pg[pix] + 1e-6f;
            float bl = pb[pix] + 1e-6f;
            float lr = logf(r), lg = logf(g), lb = logf(bl);
            float iy = sqrtf(fmaf(r, r, fmaf(g, g, bl * bl)));
            float uu, vv;
            if (ch == 0)      { uu = lr - lg; vv = lr - lb; }
            else if (ch == 1) { uu = lg - lr; vv = lg - lb; }
            else              { uu = lb - lr; vv = lb - lg; }
            u_s[p] = uu; v_s[p] = vv; w_s[p] = iy;
        }
        __syncthreads();

        for (int grp = 0; grp < SG_PIX / GRP; ++grp) {
            const int pb0 = grp * GRP;
            // ---- eval phase: fill Ku (weighted, duplicated) and Kv ----
#pragma unroll
            for (int i = 0; i < 8; ++i) {
                const int p = pbase + 4 * i;           // 0..31
                float tt  = fmaf(u_s[pb0 + p], 50.0f, -c50);
                float val = __fdividef(w_s[pb0 + p], fmaf(tt, tt, 1.0f));
                *(float2*)&ku[p * 128 + 2 * j] = make_float2(val, val);
            }
#pragma unroll
            for (int i = 0; i < 8; ++i) {
                const int p = pbase + 4 * i;
                float tt = fmaf(v_s[pb0 + p], 50.0f, -c50);
                kv[p * 64 + j] = __fdividef(1.0f, fmaf(tt, tt, 1.0f));
            }
            __syncthreads();

            // ---- accumulate: 4x4 fp32 tile per thread via f32x2 FMA ----
#pragma unroll 4
            for (int p = 0; p < GRP; ++p) {
                ulonglong2 A0 = *(const ulonglong2*)&ku[p * 128 + tr * 8];
                ulonglong2 A1 = *(const ulonglong2*)&ku[p * 128 + tr * 8 + 4];
                ulonglong2 B  = *(const ulonglong2*)&kv[p * 64 + tc * 4];
                FMA2(acc[0][0], A0.x, B.x); FMA2(acc[0][1], A0.x, B.y);
                FMA2(acc[1][0], A0.y, B.x); FMA2(acc[1][1], A0.y, B.y);
                FMA2(acc[2][0], A1.x, B.x); FMA2(acc[2][1], A1.x, B.y);
                FMA2(acc[3][0], A1.y, B.x); FMA2(acc[3][1], A1.y, B.y);
            }
            __syncthreads();
        }
    }

    // ---- write 4x4 partial tile ----
    float* out = g_part + (size_t)bid * (DH * DH);
#pragma unroll
    for (int i = 0; i < 4; ++i) {
        float4 v4;
        v4.x = lo32(acc[i][0]); v4.y = hi32(acc[i][0]);
        v4.z = lo32(acc[i][1]); v4.w = hi32(acc[i][1]);
        *(float4*)&out[(tr * 4 + i) * DH + tc * 4] = v4;
    }
}

__global__ __launch_bounds__(256) void reduce_kernel() {
    const int g = blockIdx.x;       // 0..47 : (img, b, ch)
    const int t = threadIdx.x;
    __shared__ float red[256];
    float tot = 0.0f;
    for (int bin = t; bin < DH * DH; bin += 256) {
        float s = 0.0f;
#pragma unroll
        for (int c = 0; c < CHUNKS; ++c)
            s += g_part[(size_t)(g * CHUNKS + c) * (DH * DH) + bin];
        g_hist[(size_t)g * (DH * DH) + bin] = s;
        tot += s;
    }
    red[t] = tot;
    __syncthreads();
    for (int s2 = 128; s2 > 0; s2 >>= 1) {
        if (t < s2) red[t] += red[t + s2];
        __syncthreads();
    }
    if (t == 0) g_tot[g] = red[0];
}

__global__ __launch_bounds__(256) void final_kernel(float* __restrict__ out) {
    __shared__ float red[256];
    __shared__ float invtot[16];    // [img][b]
    const int t = threadIdx.x;
    if (t < 16) {
        const int img = t >> 3, b = t & 7;
        const int g0 = (img * NB + b) * 3;
        float s = g_tot[g0] + g_tot[g0 + 1] + g_tot[g0 + 2];
        invtot[t] = 1.0f / s;
    }
    __syncthreads();
    float mean = 0.0f;
    for (int b = 0; b < NB; ++b) {
        const float itx = invtot[b];
        const float ity = invtot[8 + b];
        float local = 0.0f;
        for (int idx = t; idx < 3 * DH * DH; idx += 256) {
            const int ch = idx >> 12, bin = idx & 4095;
            float xh = g_hist[(size_t)((0 * NB + b) * 3 + ch) * (DH * DH) + bin];
            float yh = g_hist[(size_t)((1 * NB + b) * 3 + ch) * (DH * DH) + bin];
            float d = sqrtf(yh * ity) - sqrtf(xh * itx);
            local = fmaf(d, d, local);
        }
        red[t] = local;
        __syncthreads();
        for (int s2 = 128; s2 > 0; s2 >>= 1) {
            if (t < s2) red[t] += red[t + s2];
            __syncthreads();
        }
        if (t == 0) mean += sqrtf(red[0] * 0.5f);
        __syncthreads();
    }
    if (t == 0) out[0] = mean * (1.0f / (float)NB);
}

extern "C" void kernel_launch(void* const* d_in, const int* in_sizes, int n_in,
                              void* d_out, int out_size) {
    const float* x = (const float*)d_in[0];
    const float* y = (const float*)d_in[1];
    hist_kernel<<<TOT_BLOCKS, 256>>>(x, y);
    reduce_kernel<<<2 * NB * 3, 256>>>();
    final_kernel<<<1, 256>>>((float*)d_out);
}

// round 4
// speedup vs baseline: 1.2221x; 1.2221x over previous
#include <cuda_runtime.h>
#include <math.h>

// ---------------------------------------------------------------------------
// ColorHistogramMatchingLoss — R2
// 64x64 histogram per (img,batch,ch) = GEMM (64x64, K=65536) with on-the-fly
// RBF operands. R1 was LDS-crossbar bound (3 B/FMA). R2: 8x8 register tile
// per thread (64-thread groups), operands loaded NON-duplicated (1 B/FMA),
// B duplicated in registers via mov.b64, packed fma.rn.f32x2 accumulation.
// ---------------------------------------------------------------------------

#define NB        8
#define DH        64
#define CHUNKS    16
#define CHUNK_PIX 4096
#define SG_PIX    1024
#define WIN       32          // pixels per eval window
#define NPIX      65536
#define TOT_BLOCKS (2 * NB * 3 * CHUNKS)   // 768

__device__ float g_part[(size_t)TOT_BLOCKS * DH * DH];   // block partials
__device__ float g_hist[(size_t)2 * NB * 3 * DH * DH];   // 48 histograms
__device__ float g_tot[2 * NB * 3];                      // per-hist totals

#define FMA2(acc, a, b) \
    asm("fma.rn.f32x2 %0, %1, %2, %0;" : "+l"(acc) : "l"(a), "l"(b))
#define DUP(d, f) \
    asm("mov.b64 %0, {%1, %1};" : "=l"(d) : "f"(f))

__device__ __forceinline__ float lo32(unsigned long long a) {
    return __uint_as_float((unsigned int)a);
}
__device__ __forceinline__ float hi32(unsigned long long a) {
    return __uint_as_float((unsigned int)(a >> 32));
}

__global__ __launch_bounds__(256) void hist_kernel(const float* __restrict__ x,
                                                   const float* __restrict__ y) {
    __shared__ float sm[7168];                 // 28 KB
    float* u_s = sm;                           // 1024
    float* v_s = sm + 1024;                    // 1024
    float* w_s = sm + 2048;                    // 1024
    float* ku  = sm + 3072;                    // WIN*64 = 2048 (weighted)
    float* kv  = sm + 5120;                    // WIN*64 = 2048

    const int bid   = blockIdx.x;
    const int img   = bid / (NB * 3 * CHUNKS);
    const int rem   = bid % (NB * 3 * CHUNKS);
    const int b     = rem / (3 * CHUNKS);
    const int rem2  = rem % (3 * CHUNKS);
    const int ch    = rem2 / CHUNKS;
    const int chunk = rem2 % CHUNKS;

    const float* base = img ? y : x;
    const float* pr = base + (size_t)(b * 3 + 0) * NPIX + chunk * CHUNK_PIX;
    const float* pg = base + (size_t)(b * 3 + 1) * NPIX + chunk * CHUNK_PIX;
    const float* pb = base + (size_t)(b * 3 + 2) * NPIX + chunk * CHUNK_PIX;

    const int t   = threadIdx.x;
    const int j   = t & 63;                      // bin owned in eval phase
    const float c50 = (float)j * (300.0f / 63.0f) - 150.0f;  // 50 * center_j
    const int gid = t >> 6;                      // group 0..3
    const int s   = t & 63;                      // lane in group
    const int tr  = s >> 3;                      // 0..7 (8-row tile)
    const int tc  = s & 7;                       // 0..7 (8-col tile)

    // acc[rp][c] = packed (out[tr*8+2rp][tc*8+c], out[tr*8+2rp+1][tc*8+c])
    unsigned long long acc[4][8];
#pragma unroll
    for (int rp = 0; rp < 4; ++rp)
#pragma unroll
        for (int c = 0; c < 8; ++c) acc[rp][c] = 0ull;

    for (int sg = 0; sg < CHUNK_PIX / SG_PIX; ++sg) {
        __syncthreads();
        // ---- preprocess 1024 pixels: u, v, weight ----
#pragma unroll
        for (int q = 0; q < SG_PIX / 256; ++q) {
            const int p   = t + 256 * q;
            const int pix = sg * SG_PIX + p;
            float r  = pr[pix] + 1e-6f;
            float g  = pg[pix] + 1e-6f;
            float bl = pb[pix] + 1e-6f;
            float lr = __logf(r), lg = __logf(g), lb = __logf(bl);
            float iy = sqrtf(fmaf(r, r, fmaf(g, g, bl * bl)));
            float uu, vv;
            if (ch == 0)      { uu = lr - lg; vv = lr - lb; }
            else if (ch == 1) { uu = lg - lr; vv = lg - lb; }
            else              { uu = lb - lr; vv = lb - lg; }
            u_s[p] = uu; v_s[p] = vv; w_s[p] = iy;
        }
        __syncthreads();

        for (int grp = 0; grp < SG_PIX / WIN; ++grp) {
            const int pb0 = grp * WIN;
            // ---- eval: fill ku (weighted), kv for 32 pixels ----
#pragma unroll
            for (int i = 0; i < 8; ++i) {
                const int p = gid + 4 * i;          // 0..31
                float uu = u_s[pb0 + p];
                float vv = v_s[pb0 + p];
                float ww = w_s[pb0 + p];
                float tu = fmaf(uu, 50.0f, -c50);
                ku[p * 64 + j] = __fdividef(ww, fmaf(tu, tu, 1.0f));
                float tv = fmaf(vv, 50.0f, -c50);
                kv[p * 64 + j] = __fdividef(1.0f, fmaf(tv, tv, 1.0f));
            }
            __syncthreads();

            // ---- accumulate: group gid owns pixels [gid*8, gid*8+8) ----
#pragma unroll
            for (int i = 0; i < 8; ++i) {
                const int p = gid * 8 + i;
                ulonglong2 A01 = *(const ulonglong2*)&ku[p * 64 + tr * 8];
                ulonglong2 A23 = *(const ulonglong2*)&ku[p * 64 + tr * 8 + 4];
                float4 B0 = *(const float4*)&kv[p * 64 + tc * 8];
                float4 B1 = *(const float4*)&kv[p * 64 + tc * 8 + 4];
                unsigned long long bd[8];
                DUP(bd[0], B0.x); DUP(bd[1], B0.y);
                DUP(bd[2], B0.z); DUP(bd[3], B0.w);
                DUP(bd[4], B1.x); DUP(bd[5], B1.y);
                DUP(bd[6], B1.z); DUP(bd[7], B1.w);
#pragma unroll
                for (int c = 0; c < 8; ++c) {
                    FMA2(acc[0][c], A01.x, bd[c]);
                    FMA2(acc[1][c], A01.y, bd[c]);
                    FMA2(acc[2][c], A23.x, bd[c]);
                    FMA2(acc[3][c], A23.y, bd[c]);
                }
            }
            __syncthreads();
        }
    }

    // ---- unpack accumulators ----
    float res[64];
#pragma unroll
    for (int rp = 0; rp < 4; ++rp)
#pragma unroll
        for (int c = 0; c < 8; ++c) {
            res[(rp * 8 + c) * 2]     = lo32(acc[rp][c]);
            res[(rp * 8 + c) * 2 + 1] = hi32(acc[rp][c]);
        }

    // ---- cross-group reduction into group 0 (reuse sm[0..4096)) ----
    float* buf = sm;
    for (int g = 1; g < 4; ++g) {
        __syncthreads();
        if (gid == g) {
#pragma unroll
            for (int i = 0; i < 64; ++i) buf[s * 64 + i] = res[i];
        }
        __syncthreads();
        if (gid == 0) {
#pragma unroll
            for (int i = 0; i < 64; ++i) res[i] += buf[s * 64 + i];
        }
    }

    // ---- group 0 writes the block partial ----
    if (gid == 0) {
        float* out = g_part + (size_t)bid * (DH * DH);
#pragma unroll
        for (int rp = 0; rp < 4; ++rp)
#pragma unroll
            for (int c = 0; c < 8; ++c) {
#pragma unroll
                for (int h = 0; h < 2; ++h)
                    out[(tr * 8 + rp * 2 + h) * DH + tc * 8 + c] =
                        res[(rp * 8 + c) * 2 + h];
            }
    }
}

__global__ __launch_bounds__(256) void reduce_kernel() {
    const int g = blockIdx.x;       // 0..47 : (img, b, ch)
    const int t = threadIdx.x;
    __shared__ float red[256];
    float tot = 0.0f;
    for (int q = t; q < DH * DH / 4; q += 256) {       // float4 granularity
        float4 acc4 = make_float4(0.f, 0.f, 0.f, 0.f);
#pragma unroll
        for (int c = 0; c < CHUNKS; ++c) {
            float4 v = *(const float4*)&g_part[(size_t)(g * CHUNKS + c) * (DH * DH) + q * 4];
            acc4.x += v.x; acc4.y += v.y; acc4.z += v.z; acc4.w += v.w;
        }
        *(float4*)&g_hist[(size_t)g * (DH * DH) + q * 4] = acc4;
        tot += acc4.x + acc4.y + acc4.z + acc4.w;
    }
    red[t] = tot;
    __syncthreads();
    for (int s2 = 128; s2 > 0; s2 >>= 1) {
        if (t < s2) red[t] += red[t + s2];
        __syncthreads();
    }
    if (t == 0) g_tot[g] = red[0];
}

__global__ __launch_bounds__(256) void final_kernel(float* __restrict__ out) {
    __shared__ float red[256];
    __shared__ float invtot[16];    // [img][b]
    const int t = threadIdx.x;
    if (t < 16) {
        const int img = t >> 3, b = t & 7;
        const int g0 = (img * NB + b) * 3;
        float s = g_tot[g0] + g_tot[g0 + 1] + g_tot[g0 + 2];
        invtot[t] = 1.0f / s;
    }
    __syncthreads();
    float mean = 0.0f;
    for (int b = 0; b < NB; ++b) {
        const float itx = invtot[b];
        const float ity = invtot[8 + b];
        float local = 0.0f;
        for (int idx = t; idx < 3 * DH * DH; idx += 256) {
            const int ch = idx >> 12, bin = idx & 4095;
            float xh = g_hist[(size_t)((0 * NB + b) * 3 + ch) * (DH * DH) + bin];
            float yh = g_hist[(size_t)((1 * NB + b) * 3 + ch) * (DH * DH) + bin];
            float d = sqrtf(yh * ity) - sqrtf(xh * itx);
            local = fmaf(d, d, local);
        }
        red[t] = local;
        __syncthreads();
        for (int s2 = 128; s2 > 0; s2 >>= 1) {
            if (t < s2) red[t] += red[t + s2];
            __syncthreads();
        }
        if (t == 0) mean += sqrtf(red[0] * 0.5f);
        __syncthreads();
    }
    if (t == 0) out[0] = mean * (1.0f / (float)NB);
}

extern "C" void kernel_launch(void* const* d_in, const int* in_sizes, int n_in,
                              void* d_out, int out_size) {
    const float* x = (const float*)d_in[0];
    const float* y = (const float*)d_in[1];
    hist_kernel<<<TOT_BLOCKS, 256>>>(x, y);
    reduce_kernel<<<2 * NB * 3, 256>>>();
    final_kernel<<<1, 256>>>((float*)d_out);
}

// round 6
// speedup vs baseline: 1.4655x; 1.1991x over previous
#include <cuda_runtime.h>
#include <math.h>

// ---------------------------------------------------------------------------
// ColorHistogramMatchingLoss — R4
// 64x64 histogram per (img,batch,ch) = GEMM (64x64, K=65536) with on-the-fly
// RBF operands, packed fma.rn.f32x2 accumulation (8x8 register tile).
// R4: double-buffered operand tiles -> 1 barrier per 64-px window, and
// eval(w+1) ordered before acc(w) so MUFU-eval and FFMA2-acc interleave.
// tcgen05 is unavailable (harness PTX target lacks the 'a' feature suffix).
// ---------------------------------------------------------------------------

#define NB        8
#define DH        64
#define CHUNKS    16
#define CHUNK_PIX 4096
#define SG_PIX    1024
#define WIN       64
#define NWIN      (SG_PIX / WIN)     // 16
#define NPIX      65536
#define TOT_BLOCKS (2 * NB * 3 * CHUNKS)   // 768

__device__ float g_part[(size_t)TOT_BLOCKS * DH * DH];
__device__ float g_hist[(size_t)2 * NB * 3 * DH * DH];
__device__ float g_tot[2 * NB * 3];
__device__ float g_hb[NB];

// smem float offsets
#define U_OFF   0
#define V_OFF   1024
#define W_OFF   2048
#define KU_OFF(bf) (3072 + (bf) * 8192)          // 4096 floats each
#define KV_OFF(bf) (3072 + (bf) * 8192 + 4096)
#define SMEM_FLOATS (3072 + 2 * 8192)            // 19456 floats = 77824 B

#define FMA2(acc, a, b) \
    asm("fma.rn.f32x2 %0, %1, %2, %0;" : "+l"(acc) : "l"(a), "l"(b))
#define DUP(d, f) \
    asm("mov.b64 %0, {%1, %1};" : "=l"(d) : "f"(f))

__device__ __forceinline__ float frcp(float x) {
    float r; asm("rcp.approx.ftz.f32 %0, %1;" : "=f"(r) : "f"(x)); return r;
}
__device__ __forceinline__ float lo32(unsigned long long a) {
    return __uint_as_float((unsigned int)a);
}
__device__ __forceinline__ float hi32(unsigned long long a) {
    return __uint_as_float((unsigned int)(a >> 32));
}

__global__ __launch_bounds__(256, 2) void hist_kernel(const float* __restrict__ x,
                                                      const float* __restrict__ y) {
    extern __shared__ float sm[];
    float* u_s = sm + U_OFF;
    float* v_s = sm + V_OFF;
    float* w_s = sm + W_OFF;

    const int bid   = blockIdx.x;
    const int img   = bid / (NB * 3 * CHUNKS);
    const int rem   = bid % (NB * 3 * CHUNKS);
    const int b     = rem / (3 * CHUNKS);
    const int rem2  = rem % (3 * CHUNKS);
    const int ch    = rem2 / CHUNKS;
    const int chunk = rem2 % CHUNKS;

    const float* base = img ? y : x;
    const float* pr = base + (size_t)(b * 3 + 0) * NPIX + chunk * CHUNK_PIX;
    const float* pg = base + (size_t)(b * 3 + 1) * NPIX + chunk * CHUNK_PIX;
    const float* pb = base + (size_t)(b * 3 + 2) * NPIX + chunk * CHUNK_PIX;

    const int t   = threadIdx.x;
    const int j   = t & 63;                      // bin owned in eval phase
    const float c50 = (float)j * (300.0f / 63.0f) - 150.0f;  // 50 * center_j
    const int gid = t >> 6;                      // group 0..3
    const int s   = t & 63;                      // lane in group
    const int tr  = s >> 3;                      // 0..7
    const int tc  = s & 7;                       // 0..7

    unsigned long long acc[4][8];
#pragma unroll
    for (int rp = 0; rp < 4; ++rp)
#pragma unroll
        for (int c = 0; c < 8; ++c) acc[rp][c] = 0ull;

    for (int sg = 0; sg < CHUNK_PIX / SG_PIX; ++sg) {
        __syncthreads();
        // ---- preprocess 1024 pixels ----
#pragma unroll
        for (int q = 0; q < SG_PIX / 256; ++q) {
            const int p   = t + 256 * q;
            const int pix = sg * SG_PIX + p;
            float r  = pr[pix] + 1e-6f;
            float g  = pg[pix] + 1e-6f;
            float bl = pb[pix] + 1e-6f;
            float lr = __logf(r), lg = __logf(g), lb = __logf(bl);
            float iy = sqrtf(fmaf(r, r, fmaf(g, g, bl * bl)));
            float uu, vv;
            if (ch == 0)      { uu = lr - lg; vv = lr - lb; }
            else if (ch == 1) { uu = lg - lr; vv = lg - lb; }
            else              { uu = lb - lr; vv = lb - lg; }
            u_s[p] = uu; v_s[p] = vv; w_s[p] = iy;
        }
        __syncthreads();

        // ---- eval window 0 into buffer 0 ----
        {
            float* ku = sm + KU_OFF(0);
            float* kv = sm + KV_OFF(0);
#pragma unroll
            for (int i = 0; i < WIN / 4; ++i) {
                const int p = gid + 4 * i;
                float uu = u_s[p], vv = v_s[p], ww = w_s[p];
                float tu = fmaf(uu, 50.0f, -c50);
                ku[p * 64 + j] = ww * frcp(fmaf(tu, tu, 1.0f));
                float tv = fmaf(vv, 50.0f, -c50);
                kv[p * 64 + j] = frcp(fmaf(tv, tv, 1.0f));
            }
        }
        __syncthreads();

        for (int tt = 0; tt < NWIN; ++tt) {
            // ---- eval window tt+1 into buffer (tt+1)&1 (independent of acc) --
            if (tt + 1 < NWIN) {
                const int pb0 = (tt + 1) * WIN;
                float* ku = sm + KU_OFF((tt + 1) & 1);
                float* kv = sm + KV_OFF((tt + 1) & 1);
#pragma unroll
                for (int i = 0; i < WIN / 4; ++i) {
                    const int p = gid + 4 * i;
                    float uu = u_s[pb0 + p], vv = v_s[pb0 + p], ww = w_s[pb0 + p];
                    float tu = fmaf(uu, 50.0f, -c50);
                    ku[p * 64 + j] = ww * frcp(fmaf(tu, tu, 1.0f));
                    float tv = fmaf(vv, 50.0f, -c50);
                    kv[p * 64 + j] = frcp(fmaf(tv, tv, 1.0f));
                }
            }
            // ---- accumulate window tt from buffer tt&1 ----
            {
                const float* ku = sm + KU_OFF(tt & 1);
                const float* kv = sm + KV_OFF(tt & 1);
#pragma unroll 4
                for (int i = 0; i < WIN / 4; ++i) {
                    const int p = gid * (WIN / 4) + i;
                    ulonglong2 A01 = *(const ulonglong2*)&ku[p * 64 + tr * 8];
                    ulonglong2 A23 = *(const ulonglong2*)&ku[p * 64 + tr * 8 + 4];
                    float4 B0 = *(const float4*)&kv[p * 64 + tc * 8];
                    float4 B1 = *(const float4*)&kv[p * 64 + tc * 8 + 4];
                    unsigned long long bd[8];
                    DUP(bd[0], B0.x); DUP(bd[1], B0.y);
                    DUP(bd[2], B0.z); DUP(bd[3], B0.w);
                    DUP(bd[4], B1.x); DUP(bd[5], B1.y);
                    DUP(bd[6], B1.z); DUP(bd[7], B1.w);
#pragma unroll
                    for (int c = 0; c < 8; ++c) {
                        FMA2(acc[0][c], A01.x, bd[c]);
                        FMA2(acc[1][c], A01.y, bd[c]);
                        FMA2(acc[2][c], A23.x, bd[c]);
                        FMA2(acc[3][c], A23.y, bd[c]);
                    }
                }
            }
            __syncthreads();
        }
    }

    // ---- unpack accumulators ----
    float res[64];
#pragma unroll
    for (int rp = 0; rp < 4; ++rp)
#pragma unroll
        for (int c = 0; c < 8; ++c) {
            res[(rp * 8 + c) * 2]     = lo32(acc[rp][c]);
            res[(rp * 8 + c) * 2 + 1] = hi32(acc[rp][c]);
        }

    // ---- cross-group reduction into group 0 ----
    float* buf = sm;
    for (int g = 1; g < 4; ++g) {
        __syncthreads();
        if (gid == g) {
#pragma unroll
            for (int i = 0; i < 64; ++i) buf[s * 64 + i] = res[i];
        }
        __syncthreads();
        if (gid == 0) {
#pragma unroll
            for (int i = 0; i < 64; ++i) res[i] += buf[s * 64 + i];
        }
    }

    if (gid == 0) {
        float* out = g_part + (size_t)bid * (DH * DH);
#pragma unroll
        for (int rp = 0; rp < 4; ++rp)
#pragma unroll
            for (int c = 0; c < 8; ++c) {
#pragma unroll
                for (int h = 0; h < 2; ++h)
                    out[(tr * 8 + rp * 2 + h) * DH + tc * 8 + c] =
                        res[(rp * 8 + c) * 2 + h];
            }
    }
}

__global__ __launch_bounds__(256) void reduce_kernel() {
    const int g = blockIdx.x;       // 0..47 : (img, b, ch)
    const int t = threadIdx.x;
    __shared__ float red[256];
    float tot = 0.0f;
    for (int q = t; q < DH * DH / 4; q += 256) {
        float4 a4 = make_float4(0.f, 0.f, 0.f, 0.f);
#pragma unroll
        for (int c = 0; c < CHUNKS; ++c) {
            float4 v = *(const float4*)&g_part[(size_t)(g * CHUNKS + c) * (DH * DH) + q * 4];
            a4.x += v.x; a4.y += v.y; a4.z += v.z; a4.w += v.w;
        }
        *(float4*)&g_hist[(size_t)g * (DH * DH) + q * 4] = a4;
        tot += a4.x + a4.y + a4.z + a4.w;
    }
    red[t] = tot;
    __syncthreads();
    for (int s2 = 128; s2 > 0; s2 >>= 1) {
        if (t < s2) red[t] += red[t + s2];
        __syncthreads();
    }
    if (t == 0) g_tot[g] = red[0];
}

__global__ __launch_bounds__(256) void final_part_kernel() {
    const int b = blockIdx.x;            // 0..7
    const int t = threadIdx.x;
    __shared__ float red[256];
    const float itx = 1.0f / (g_tot[b * 3] + g_tot[b * 3 + 1] + g_tot[b * 3 + 2]);
    const int g0y = (NB + b) * 3;
    const float ity = 1.0f / (g_tot[g0y] + g_tot[g0y + 1] + g_tot[g0y + 2]);
    float local = 0.0f;
    for (int idx = t; idx < 3 * DH * DH; idx += 256) {
        const int ch = idx >> 12, bin = idx & 4095;
        float xh = g_hist[(size_t)(b * 3 + ch) * (DH * DH) + bin];
        float yh = g_hist[(size_t)((NB + b) * 3 + ch) * (DH * DH) + bin];
        float d = sqrtf(yh * ity) - sqrtf(xh * itx);
        local = fmaf(d, d, local);
    }
    red[t] = local;
    __syncthreads();
    for (int s2 = 128; s2 > 0; s2 >>= 1) {
        if (t < s2) red[t] += red[t + s2];
        __syncthreads();
    }
    if (t == 0) g_hb[b] = sqrtf(red[0] * 0.5f);
}

__global__ void final_sum_kernel(float* __restrict__ out) {
    if (threadIdx.x == 0) {
        float m = 0.0f;
#pragma unroll
        for (int b = 0; b < NB; ++b) m += g_hb[b];
        out[0] = m * (1.0f / (float)NB);
    }
}

extern "C" void kernel_launch(void* const* d_in, const int* in_sizes, int n_in,
                              void* d_out, int out_size) {
    const float* x = (const float*)d_in[0];
    const float* y = (const float*)d_in[1];
    cudaFuncSetAttribute(hist_kernel, cudaFuncAttributeMaxDynamicSharedMemorySize,
                         SMEM_FLOATS * 4);
    hist_kernel<<<TOT_BLOCKS, 256, SMEM_FLOATS * 4>>>(x, y);
    reduce_kernel<<<2 * NB * 3, 256>>>();
    final_part_kernel<<<NB, 256>>>();
    final_sum_kernel<<<1, 32>>>((float*)d_out);
}

// round 7
// speedup vs baseline: 2.8483x; 1.9436x over previous
#include <cuda_runtime.h>
#include <cstdint>
#include <math.h>

// ---------------------------------------------------------------------------
// ColorHistogramMatchingLoss — R5 (mma.sync bf16 HMMA, hi/lo split)
// hist[u,v] = sum_p w_p*Ku[u,p]*Kv[v,p] = GEMM 64x64, K=65536 (x48 hists).
// bf16 split: A=[Ah;Al] stacked 128xK; D += Astack*Bh^T (all), += Ah*Bl^T
// (warps 0-3). Fold rows u and u+64. Swizzled k-major smem tiles,
// double-buffered eval/mma pipeline, 1 barrier per 64-px window.
// ---------------------------------------------------------------------------

#define NB        8
#define DH        64
#define CHUNKS    16
#define CHUNK_PIX 4096
#define SG_PIX    1024
#define WIN       64
#define NWIN      (SG_PIX / WIN)
#define NPIX      65536
#define TOT_BLOCKS (2 * NB * 3 * CHUNKS)   // 768

__device__ float g_part[(size_t)TOT_BLOCKS * DH * DH];
__device__ float g_hist[(size_t)2 * NB * 3 * DH * DH];
__device__ float g_tot[2 * NB * 3];
__device__ float g_hb[NB];

// byte offsets in dynamic smem
#define UO 0
#define VO 4096
#define WO 8192
#define AO(bf)  (12288 + (bf) * 16384)   // 128 rows x 128B
#define BHO(bf) (45056 + (bf) * 8192)    // 64 rows x 128B
#define BLO(bf) (61440 + (bf) * 8192)
#define EPIL    12288                    // 64x64 f32 (reuses A0)
#define SMEM_BYTES 77824

// swizzled byte offset within a tile (row stride 128B)
__device__ __forceinline__ uint32_t toff(int row, int c) {
    return (uint32_t)(row * 128 + (c ^ ((row & 7) << 4)));
}
__device__ __forceinline__ float frcp(float x) {
    float r; asm("rcp.approx.ftz.f32 %0, %1;" : "=f"(r) : "f"(x)); return r;
}
// res = [bf16(hi) : bf16(lo)]  (low half = lo)
#define PACK2(res, lo, hi) \
    asm("cvt.rn.satfinite.bf16x2.f32 %0, %1, %2;" : "=r"(res) : "f"(hi), "f"(lo))

#define MMA(d, a0, a1, a2, a3, b0, b1)                                        \
    asm volatile("mma.sync.aligned.m16n8k16.row.col.f32.bf16.bf16.f32 "       \
                 "{%0,%1,%2,%3}, {%4,%5,%6,%7}, {%8,%9}, {%0,%1,%2,%3};"      \
                 : "+f"((d)[0]), "+f"((d)[1]), "+f"((d)[2]), "+f"((d)[3])     \
                 : "r"(a0), "r"(a1), "r"(a2), "r"(a3), "r"(b0), "r"(b1))

__global__ __launch_bounds__(256, 2) void hist_kernel(const float* __restrict__ x,
                                                      const float* __restrict__ y) {
    extern __shared__ char smem[];
    float* u_s = (float*)(smem + UO);
    float* v_s = (float*)(smem + VO);
    float* w_s = (float*)(smem + WO);

    const int bid   = blockIdx.x;
    const int img   = bid / (NB * 3 * CHUNKS);
    const int rem   = bid % (NB * 3 * CHUNKS);
    const int b     = rem / (3 * CHUNKS);
    const int rem2  = rem % (3 * CHUNKS);
    const int ch    = rem2 / CHUNKS;
    const int chunk = rem2 % CHUNKS;

    const float* base = img ? y : x;
    const float* pr = base + (size_t)(b * 3 + 0) * NPIX + chunk * CHUNK_PIX;
    const float* pg = base + (size_t)(b * 3 + 1) * NPIX + chunk * CHUNK_PIX;
    const float* pb = base + (size_t)(b * 3 + 2) * NPIX + chunk * CHUNK_PIX;

    const int t = threadIdx.x;
    const int w = t >> 5;               // warp 0..7
    const int L = t & 31;               // lane
    const float CK = 300.0f / 63.0f;

    float d[8][4];
#pragma unroll
    for (int nt = 0; nt < 8; ++nt)
#pragma unroll
        for (int i = 0; i < 4; ++i) d[nt][i] = 0.0f;

    // --- eval of window `tt` of current SG into buffer bf ---
    auto eval_win = [&](int px0, int bf) {
        char* A  = smem + AO(bf);
        char* BH = smem + BHO(bf);
        char* BL = smem + BLO(bf);
        const float2 up = *(const float2*)&u_s[px0 + 2 * L];
        const float2 vp = *(const float2*)&v_s[px0 + 2 * L];
        const float2 wp = *(const float2*)&w_s[px0 + 2 * L];
#pragma unroll
        for (int jj = 0; jj < 8; ++jj) {
            const int j = w * 8 + jj;
            const float c50 = (float)j * CK - 150.0f;
            const uint32_t ro = toff(j, 4 * L);
            // A side (u, weighted)
            float t0 = fmaf(up.x, 50.0f, -c50), t1 = fmaf(up.y, 50.0f, -c50);
            float a0 = wp.x * frcp(fmaf(t0, t0, 1.0f));
            float a1 = wp.y * frcp(fmaf(t1, t1, 1.0f));
            uint32_t ha; PACK2(ha, a0, a1);
            float r0 = a0 - __uint_as_float(ha << 16);
            float r1 = a1 - __uint_as_float(ha & 0xFFFF0000u);
            uint32_t la; PACK2(la, r0, r1);
            *(uint32_t*)(A + ro)                = ha;
            *(uint32_t*)(A + toff(j + 64, 4 * L)) = la;
            // B side (v)
            float s0 = fmaf(vp.x, 50.0f, -c50), s1 = fmaf(vp.y, 50.0f, -c50);
            float b0 = frcp(fmaf(s0, s0, 1.0f));
            float b1 = frcp(fmaf(s1, s1, 1.0f));
            uint32_t hb; PACK2(hb, b0, b1);
            float q0 = b0 - __uint_as_float(hb << 16);
            float q1 = b1 - __uint_as_float(hb & 0xFFFF0000u);
            uint32_t lb; PACK2(lb, q0, q1);
            *(uint32_t*)(BH + ro) = hb;
            *(uint32_t*)(BL + ro) = lb;
        }
    };

    // --- mma over buffer bf ---
    auto mma_win = [&](int bf) {
        const char* A  = smem + AO(bf);
        const char* BH = smem + BHO(bf);
        const char* BL = smem + BLO(bf);
        const int ra = 16 * w + (L >> 2);
        const int rb = L >> 2;
#pragma unroll
        for (int s = 0; s < 4; ++s) {
            const int ca = s * 32 + (L & 3) * 4;
            uint32_t a0 = *(const uint32_t*)(A + toff(ra, ca));
            uint32_t a1 = *(const uint32_t*)(A + toff(ra + 8, ca));
            uint32_t a2 = *(const uint32_t*)(A + toff(ra, ca + 16));
            uint32_t a3 = *(const uint32_t*)(A + toff(ra + 8, ca + 16));
#pragma unroll
            for (int nt = 0; nt < 8; ++nt) {
                uint32_t b0 = *(const uint32_t*)(BH + toff(nt * 8 + rb, ca));
                uint32_t b1 = *(const uint32_t*)(BH + toff(nt * 8 + rb, ca + 16));
                MMA(d[nt], a0, a1, a2, a3, b0, b1);
            }
            if (w < 4) {
#pragma unroll
                for (int nt = 0; nt < 8; ++nt) {
                    uint32_t b0 = *(const uint32_t*)(BL + toff(nt * 8 + rb, ca));
                    uint32_t b1 = *(const uint32_t*)(BL + toff(nt * 8 + rb, ca + 16));
                    MMA(d[nt], a0, a1, a2, a3, b0, b1);
                }
            }
        }
    };

    for (int sg = 0; sg < CHUNK_PIX / SG_PIX; ++sg) {
        __syncthreads();
#pragma unroll
        for (int q = 0; q < SG_PIX / 256; ++q) {
            const int p   = t + 256 * q;
            const int pix = sg * SG_PIX + p;
            float r  = pr[pix] + 1e-6f;
            float g  = pg[pix] + 1e-6f;
            float bl = pb[pix] + 1e-6f;
            float lr = __logf(r), lg = __logf(g), lb = __logf(bl);
            float iy = sqrtf(fmaf(r, r, fmaf(g, g, bl * bl)));
            float uu, vv;
            if (ch == 0)      { uu = lr - lg; vv = lr - lb; }
            else if (ch == 1) { uu = lg - lr; vv = lg - lb; }
            else              { uu = lb - lr; vv = lb - lg; }
            u_s[p] = uu; v_s[p] = vv; w_s[p] = iy;
        }
        __syncthreads();

        eval_win(0, 0);
        __syncthreads();
        for (int tt = 0; tt < NWIN; ++tt) {
            if (tt + 1 < NWIN) eval_win((tt + 1) * WIN, (tt + 1) & 1);
            mma_win(tt & 1);
            __syncthreads();
        }
    }

    // ---- epilogue: fold D[u] + D[u+64] ----
    float* epil = (float*)(smem + EPIL);
    const int rg = L >> 2;
    const int cg = (L & 3) * 2;
    if (w >= 4) {
        const int r0 = 16 * (w - 4) + rg;
#pragma unroll
        for (int nt = 0; nt < 8; ++nt) {
            const int c = nt * 8 + cg;
            epil[r0 * 64 + c]           = d[nt][0];
            epil[r0 * 64 + c + 1]       = d[nt][1];
            epil[(r0 + 8) * 64 + c]     = d[nt][2];
            epil[(r0 + 8) * 64 + c + 1] = d[nt][3];
        }
    }
    __syncthreads();
    if (w < 4) {
        const int r0 = 16 * w + rg;
        float* out = g_part + (size_t)bid * (DH * DH);
#pragma unroll
        for (int nt = 0; nt < 8; ++nt) {
            const int c = nt * 8 + cg;
            out[r0 * 64 + c]           = d[nt][0] + epil[r0 * 64 + c];
            out[r0 * 64 + c + 1]       = d[nt][1] + epil[r0 * 64 + c + 1];
            out[(r0 + 8) * 64 + c]     = d[nt][2] + epil[(r0 + 8) * 64 + c];
            out[(r0 + 8) * 64 + c + 1] = d[nt][3] + epil[(r0 + 8) * 64 + c + 1];
        }
    }
}

__global__ __launch_bounds__(256) void reduce_kernel() {
    const int g = blockIdx.x;
    const int t = threadIdx.x;
    __shared__ float red[256];
    float tot = 0.0f;
    for (int q = t; q < DH * DH / 4; q += 256) {
        float4 a4 = make_float4(0.f, 0.f, 0.f, 0.f);
#pragma unroll
        for (int c = 0; c < CHUNKS; ++c) {
            float4 v = *(const float4*)&g_part[(size_t)(g * CHUNKS + c) * (DH * DH) + q * 4];
            a4.x += v.x; a4.y += v.y; a4.z += v.z; a4.w += v.w;
        }
        *(float4*)&g_hist[(size_t)g * (DH * DH) + q * 4] = a4;
        tot += a4.x + a4.y + a4.z + a4.w;
    }
    red[t] = tot;
    __syncthreads();
    for (int s2 = 128; s2 > 0; s2 >>= 1) {
        if (t < s2) red[t] += red[t + s2];
        __syncthreads();
    }
    if (t == 0) g_tot[g] = red[0];
}

__global__ __launch_bounds__(256) void final_part_kernel() {
    const int b = blockIdx.x;
    const int t = threadIdx.x;
    __shared__ float red[256];
    const float itx = 1.0f / (g_tot[b * 3] + g_tot[b * 3 + 1] + g_tot[b * 3 + 2]);
    const int g0y = (NB + b) * 3;
    const float ity = 1.0f / (g_tot[g0y] + g_tot[g0y + 1] + g_tot[g0y + 2]);
    float local = 0.0f;
    for (int idx = t; idx < 3 * DH * DH; idx += 256) {
        const int ch = idx >> 12, bin = idx & 4095;
        float xh = g_hist[(size_t)(b * 3 + ch) * (DH * DH) + bin];
        float yh = g_hist[(size_t)((NB + b) * 3 + ch) * (DH * DH) + bin];
        float dd = sqrtf(yh * ity) - sqrtf(xh * itx);
        local = fmaf(dd, dd, local);
    }
    red[t] = local;
    __syncthreads();
    for (int s2 = 128; s2 > 0; s2 >>= 1) {
        if (t < s2) red[t] += red[t + s2];
        __syncthreads();
    }
    if (t == 0) g_hb[b] = sqrtf(red[0] * 0.5f);
}

__global__ void final_sum_kernel(float* __restrict__ out) {
    if (threadIdx.x == 0) {
        float m = 0.0f;
#pragma unroll
        for (int b = 0; b < NB; ++b) m += g_hb[b];
        out[0] = m * (1.0f / (float)NB);
    }
}

extern "C" void kernel_launch(void* const* d_in, const int* in_sizes, int n_in,
                              void* d_out, int out_size) {
    const float* x = (const float*)d_in[0];
    const float* y = (const float*)d_in[1];
    cudaFuncSetAttribute(hist_kernel, cudaFuncAttributeMaxDynamicSharedMemorySize,
                         SMEM_BYTES);
    hist_kernel<<<TOT_BLOCKS, 256, SMEM_BYTES>>>(x, y);
    reduce_kernel<<<2 * NB * 3, 256>>>();
    final_part_kernel<<<NB, 256>>>();
    final_sum_kernel<<<1, 32>>>((float*)d_out);
}

// round 8
// speedup vs baseline: 3.2563x; 1.1433x over previous
#include <cuda_runtime.h>
#include <cstdint>
#include <math.h>

// ---------------------------------------------------------------------------
// ColorHistogramMatchingLoss — R6
// bf16 hi/lo split HMMA (mma.sync m16n8k16) histogram GEMM.
// R6: ldmatrix.x4 fragment loads, Bl work balanced across all 8 warps
// (fold-legality), packed f32x2 eval, 3 blocks/SM (smaller staging),
// per-s eval/mma software pipeline.
// ---------------------------------------------------------------------------

#define NB        8
#define DH        64
#define CHUNKS    16
#define CHUNK_PIX 4096
#define SG_PIX    512
#define WIN       64
#define NWIN      (SG_PIX / WIN)      // 8
#define NPIX      65536
#define TOT_BLOCKS (2 * NB * 3 * CHUNKS)   // 768

__device__ float g_part[(size_t)TOT_BLOCKS * DH * DH];
__device__ float g_hist[(size_t)2 * NB * 3 * DH * DH];
__device__ float g_tot[2 * NB * 3];
__device__ float g_hb[NB];

typedef unsigned long long ull;

// byte offsets in dynamic smem
#define UO 0
#define VO 2048
#define WO 4096
#define AO(bf)  (6144 + (bf) * 32768)            // 128 rows x 128B
#define BHO(bf) (6144 + (bf) * 32768 + 16384)    // 64 rows x 128B
#define BLO(bf) (6144 + (bf) * 32768 + 24576)
#define EPIL    AO(0)
#define SMEM_BYTES (6144 + 2 * 32768)            // 71680

__device__ __forceinline__ uint32_t s2u(const void* p) {
    uint32_t a;
    asm("{ .reg .u64 t; cvta.to.shared.u64 t, %1; cvt.u32.u64 %0, t; }"
        : "=r"(a) : "l"(p));
    return a;
}
__device__ __forceinline__ float frcp(float x) {
    float r; asm("rcp.approx.ftz.f32 %0, %1;" : "=f"(r) : "f"(x)); return r;
}
// res = [bf16(hi) : bf16(lo)]
#define PACK2(res, lo, hi) \
    asm("cvt.rn.satfinite.bf16x2.f32 %0, %1, %2;" : "=r"(res) : "f"(hi), "f"(lo))
#define F2FMA(d, a, b, c) \
    asm("fma.rn.f32x2 %0, %1, %2, %3;" : "=l"(d) : "l"(a), "l"(b), "l"(c))
#define DUPU(d, u) \
    asm("mov.b64 %0, {%1, %1};" : "=l"(d) : "r"(u))
#define UNPK(lo, hi, v) \
    asm("mov.b64 {%0, %1}, %2;" : "=r"(lo), "=r"(hi) : "l"(v))

#define LDSM4(r, addr)                                                        \
    asm volatile("ldmatrix.sync.aligned.m8n8.x4.shared.b16 {%0,%1,%2,%3}, [%4];" \
                 : "=r"((r)[0]), "=r"((r)[1]), "=r"((r)[2]), "=r"((r)[3])     \
                 : "r"(addr))
#define STS32(addr, v) \
    asm volatile("st.shared.b32 [%0], %1;" :: "r"(addr), "r"(v) : "memory")

#define MMA(dd, a0, a1, a2, a3, b0, b1)                                       \
    asm volatile("mma.sync.aligned.m16n8k16.row.col.f32.bf16.bf16.f32 "       \
                 "{%0,%1,%2,%3}, {%4,%5,%6,%7}, {%8,%9}, {%0,%1,%2,%3};"      \
                 : "+f"((dd)[0]), "+f"((dd)[1]), "+f"((dd)[2]), "+f"((dd)[3]) \
                 : "r"(a0), "r"(a1), "r"(a2), "r"(a3), "r"(b0), "r"(b1))

__global__ __launch_bounds__(256, 3) void hist_kernel(const float* __restrict__ x,
                                                      const float* __restrict__ y) {
    extern __shared__ char smem[];
    const uint32_t sb = s2u(smem);
    float* u_s = (float*)(smem + UO);
    float* v_s = (float*)(smem + VO);
    float* w_s = (float*)(smem + WO);

    const int bid   = blockIdx.x;
    const int img   = bid / (NB * 3 * CHUNKS);
    const int rem   = bid % (NB * 3 * CHUNKS);
    const int b     = rem / (3 * CHUNKS);
    const int rem2  = rem % (3 * CHUNKS);
    const int ch    = rem2 / CHUNKS;
    const int chunk = rem2 % CHUNKS;

    const float* base = img ? y : x;
    const float* pr = base + (size_t)(b * 3 + 0) * NPIX + chunk * CHUNK_PIX;
    const float* pg = base + (size_t)(b * 3 + 1) * NPIX + chunk * CHUNK_PIX;
    const float* pb = base + (size_t)(b * 3 + 2) * NPIX + chunk * CHUNK_PIX;

    const int t = threadIdx.x;
    const int w = t >> 5;
    const int L = t & 31;
    const float CK = 300.0f / 63.0f;

    // ldmatrix lane addressing (byte units)
    const int mrow  = L & 7;
    const int msel  = L >> 3;                 // 0..3
    const uint32_t swz = (uint32_t)(mrow << 4);
    const uint32_t rowA  = (uint32_t)((16 * w + mrow + (msel & 1) * 8) * 128);
    const uint32_t rowAh = (uint32_t)((16 * (w & 3) + mrow + (msel & 1) * 8) * 128);
    const uint32_t kaddA = (uint32_t)((msel >> 1) * 16);
    const uint32_t rowBb = (uint32_t)(((msel >> 1) * 8 + mrow) * 128);
    const uint32_t kaddB = (uint32_t)((msel & 1) * 16);
    // eval store addressing
    const uint32_t fourL = (uint32_t)(4 * L);
    const uint32_t wrow  = (uint32_t)(w * 8 * 128);

    const ull K50  = 0x4248000042480000ull;   // {50, 50}
    const ull ONE2 = 0x3F8000003F800000ull;   // {1, 1}

    float d[8][4];
#pragma unroll
    for (int nt = 0; nt < 8; ++nt)
#pragma unroll
        for (int i = 0; i < 4; ++i) d[nt][i] = 0.0f;

    // ---- eval two bins (jj, jj+1 handled by separate calls) ----
    auto ev1 = [&](int jj, ull Un, ull Vn, float wnx, float wny,
                   uint32_t aB, uint32_t bhB, uint32_t blB) {
        const float c50 = (float)(w * 8 + jj) * CK - 150.0f;
        ull C2; DUPU(C2, __float_as_uint(-c50));
        const uint32_t ro = wrow + (uint32_t)(jj * 128) + (fourL ^ (uint32_t)(jj << 4));
        ull T, S; uint32_t s0i, s1i;
        // A side
        F2FMA(T, Un, K50, C2);
        F2FMA(S, T, T, ONE2);
        UNPK(s0i, s1i, S);
        float r0 = frcp(__uint_as_float(s0i)) * wnx;
        float r1 = frcp(__uint_as_float(s1i)) * wny;
        uint32_t ha; PACK2(ha, r0, r1);
        float e0 = r0 - __uint_as_float(ha << 16);
        float e1 = r1 - __uint_as_float(ha & 0xFFFF0000u);
        uint32_t la; PACK2(la, e0, e1);
        STS32(aB + ro, ha);
        STS32(aB + 64 * 128 + ro, la);
        // B side
        F2FMA(T, Vn, K50, C2);
        F2FMA(S, T, T, ONE2);
        UNPK(s0i, s1i, S);
        float b0 = frcp(__uint_as_float(s0i));
        float b1 = frcp(__uint_as_float(s1i));
        uint32_t hb; PACK2(hb, b0, b1);
        float f0 = b0 - __uint_as_float(hb << 16);
        float f1 = b1 - __uint_as_float(hb & 0xFFFF0000u);
        uint32_t lb; PACK2(lb, f0, f1);
        STS32(bhB + ro, hb);
        STS32(blB + ro, lb);
    };

    // ---- one k16 mma step over buffer ----
    auto mma_s = [&](int s, uint32_t aB, uint32_t bhB, uint32_t blB) {
        const uint32_t ca = (uint32_t)(s * 32);
        uint32_t a[4], bf_[4];
        LDSM4(a, aB + rowA + ((ca + kaddA) ^ swz));
#pragma unroll
        for (int ntp = 0; ntp < 4; ++ntp) {
            LDSM4(bf_, bhB + (uint32_t)(ntp * 16 * 128) + rowBb + ((ca + kaddB) ^ swz));
            MMA(d[2 * ntp],     a[0], a[1], a[2], a[3], bf_[0], bf_[1]);
            MMA(d[2 * ntp + 1], a[0], a[1], a[2], a[3], bf_[2], bf_[3]);
        }
        if (w < 4) {
#pragma unroll
            for (int ntp = 0; ntp < 2; ++ntp) {
                LDSM4(bf_, blB + (uint32_t)(ntp * 16 * 128) + rowBb + ((ca + kaddB) ^ swz));
                MMA(d[2 * ntp],     a[0], a[1], a[2], a[3], bf_[0], bf_[1]);
                MMA(d[2 * ntp + 1], a[0], a[1], a[2], a[3], bf_[2], bf_[3]);
            }
        } else {
            uint32_t h[4];
            LDSM4(h, aB + rowAh + ((ca + kaddA) ^ swz));
#pragma unroll
            for (int ntp = 2; ntp < 4; ++ntp) {
                LDSM4(bf_, blB + (uint32_t)(ntp * 16 * 128) + rowBb + ((ca + kaddB) ^ swz));
                MMA(d[2 * ntp],     h[0], h[1], h[2], h[3], bf_[0], bf_[1]);
                MMA(d[2 * ntp + 1], h[0], h[1], h[2], h[3], bf_[2], bf_[3]);
            }
        }
    };

    for (int sg = 0; sg < CHUNK_PIX / SG_PIX; ++sg) {
        __syncthreads();
#pragma unroll
        for (int q = 0; q < SG_PIX / 256; ++q) {
            const int p   = t + 256 * q;
            const int pix = sg * SG_PIX + p;
            float r  = pr[pix] + 1e-6f;
            float g  = pg[pix] + 1e-6f;
            float bl = pb[pix] + 1e-6f;
            float lr = __logf(r), lg = __logf(g), lb = __logf(bl);
            float iy = sqrtf(fmaf(r, r, fmaf(g, g, bl * bl)));
            float uu, vv;
            if (ch == 0)      { uu = lr - lg; vv = lr - lb; }
            else if (ch == 1) { uu = lg - lr; vv = lg - lb; }
            else              { uu = lb - lr; vv = lb - lg; }
            u_s[p] = uu; v_s[p] = vv; w_s[p] = iy;
        }
        __syncthreads();

        // prologue: eval window 0 into buffer 0
        {
            ull Un = *(const ull*)&u_s[2 * L];
            ull Vn = *(const ull*)&v_s[2 * L];
            float2 wp = *(const float2*)&w_s[2 * L];
            const uint32_t aB = sb + AO(0), bhB = sb + BHO(0), blB = sb + BLO(0);
#pragma unroll
            for (int jj = 0; jj < 8; ++jj) ev1(jj, Un, Vn, wp.x, wp.y, aB, bhB, blB);
        }
        __syncthreads();

        for (int tt = 0; tt < NWIN; ++tt) {
            const uint32_t cb = (uint32_t)(tt & 1);
            const uint32_t nb_ = cb ^ 1u;
            const uint32_t aB  = sb + AO(cb),  bhB  = sb + BHO(cb),  blB  = sb + BLO(cb);
            const uint32_t aBn = sb + AO(nb_), bhBn = sb + BHO(nb_), blBn = sb + BLO(nb_);
            const bool have_next = (tt + 1 < NWIN);
            ull Un = 0, Vn = 0; float2 wp = make_float2(0.f, 0.f);
            if (have_next) {
                const int px0 = (tt + 1) * WIN;
                Un = *(const ull*)&u_s[px0 + 2 * L];
                Vn = *(const ull*)&v_s[px0 + 2 * L];
                wp = *(const float2*)&w_s[px0 + 2 * L];
            }
#pragma unroll
            for (int s = 0; s < 4; ++s) {
                if (have_next) {
                    ev1(2 * s,     Un, Vn, wp.x, wp.y, aBn, bhBn, blBn);
                    ev1(2 * s + 1, Un, Vn, wp.x, wp.y, aBn, bhBn, blBn);
                }
                mma_s(s, aB, bhB, blB);
            }
            __syncthreads();
        }
    }

    // ---- epilogue: fold D[u] + D[u+64] ----
    float* epil = (float*)(smem + EPIL);
    const int rg = L >> 2;
    const int cg = (L & 3) * 2;
    if (w >= 4) {
        const int r0 = 16 * (w - 4) + rg;
#pragma unroll
        for (int nt = 0; nt < 8; ++nt) {
            const int c = nt * 8 + cg;
            epil[r0 * 64 + c]           = d[nt][0];
            epil[r0 * 64 + c + 1]       = d[nt][1];
            epil[(r0 + 8) * 64 + c]     = d[nt][2];
            epil[(r0 + 8) * 64 + c + 1] = d[nt][3];
        }
    }
    __syncthreads();
    if (w < 4) {
        const int r0 = 16 * w + rg;
        float* out = g_part + (size_t)bid * (DH * DH);
#pragma unroll
        for (int nt = 0; nt < 8; ++nt) {
            const int c = nt * 8 + cg;
            out[r0 * 64 + c]           = d[nt][0] + epil[r0 * 64 + c];
            out[r0 * 64 + c + 1]       = d[nt][1] + epil[r0 * 64 + c + 1];
            out[(r0 + 8) * 64 + c]     = d[nt][2] + epil[(r0 + 8) * 64 + c];
            out[(r0 + 8) * 64 + c + 1] = d[nt][3] + epil[(r0 + 8) * 64 + c + 1];
        }
    }
}

__global__ __launch_bounds__(256) void reduce_kernel() {
    const int g = blockIdx.x;
    const int t = threadIdx.x;
    __shared__ float red[256];
    float tot = 0.0f;
    for (int q = t; q < DH * DH / 4; q += 256) {
        float4 a4 = make_float4(0.f, 0.f, 0.f, 0.f);
#pragma unroll
        for (int c = 0; c < CHUNKS; ++c) {
            float4 v = *(const float4*)&g_part[(size_t)(g * CHUNKS + c) * (DH * DH) + q * 4];
            a4.x += v.x; a4.y += v.y; a4.z += v.z; a4.w += v.w;
        }
        *(float4*)&g_hist[(size_t)g * (DH * DH) + q * 4] = a4;
        tot += a4.x + a4.y + a4.z + a4.w;
    }
    red[t] = tot;
    __syncthreads();
    for (int s2 = 128; s2 > 0; s2 >>= 1) {
        if (t < s2) red[t] += red[t + s2];
        __syncthreads();
    }
    if (t == 0) g_tot[g] = red[0];
}

__global__ __launch_bounds__(256) void final_part_kernel() {
    const int b = blockIdx.x;
    const int t = threadIdx.x;
    __shared__ float red[256];
    const float itx = 1.0f / (g_tot[b * 3] + g_tot[b * 3 + 1] + g_tot[b * 3 + 2]);
    const int g0y = (NB + b) * 3;
    const float ity = 1.0f / (g_tot[g0y] + g_tot[g0y + 1] + g_tot[g0y + 2]);
    float local = 0.0f;
    for (int idx = t; idx < 3 * DH * DH; idx += 256) {
        const int ch = idx >> 12, bin = idx & 4095;
        float xh = g_hist[(size_t)(b * 3 + ch) * (DH * DH) + bin];
        float yh = g_hist[(size_t)((NB + b) * 3 + ch) * (DH * DH) + bin];
        float dd = sqrtf(yh * ity) - sqrtf(xh * itx);
        local = fmaf(dd, dd, local);
    }
    red[t] = local;
    __syncthreads();
    for (int s2 = 128; s2 > 0; s2 >>= 1) {
        if (t < s2) red[t] += red[t + s2];
        __syncthreads();
    }
    if (t == 0) g_hb[b] = sqrtf(red[0] * 0.5f);
}

__global__ void final_sum_kernel(float* __restrict__ out) {
    if (threadIdx.x == 0) {
        float m = 0.0f;
#pragma unroll
        for (int b = 0; b < NB; ++b) m += g_hb[b];
        out[0] = m * (1.0f / (float)NB);
    }
}

extern "C" void kernel_launch(void* const* d_in, const int* in_sizes, int n_in,
                              void* d_out, int out_size) {
    const float* x = (const float*)d_in[0];
    const float* y = (const float*)d_in[1];
    cudaFuncSetAttribute(hist_kernel, cudaFuncAttributeMaxDynamicSharedMemorySize,
                         SMEM_BYTES);
    hist_kernel<<<TOT_BLOCKS, 256, SMEM_BYTES>>>(x, y);
    reduce_kernel<<<2 * NB * 3, 256>>>();
    final_part_kernel<<<NB, 256>>>();
    final_sum_kernel<<<1, 32>>>((float*)d_out);
}